// round 12
// baseline (speedup 1.0000x reference)
#include <cuda_runtime.h>
#include <cuda_bf16.h>

// Single fused kernel, 256 threads / 8 warps, 2 batches per warp.
// The class-presence mask lives in registers (every lane, via
// __reduce_or_sync) and never touches shared memory.
//
// Presence decided from a 256-element sampled prefix per batch (32 lanes x
// 2 int4). If the sampled mask is full, remaining labels provably cannot
// change the (monotone) OR; miss prob ~1.9e-5/batch on uniform labels. An
// unsaturated batch is scanned by its owning warp alone (chunked,
// warp-uniform early exit) -- correct for arbitrary inputs. Decision depends
// only on input data: same inputs -> same work -> same output.
//
// Critical-path layout:
//  - 4 int4 LDGs issued back-to-back (MLP 4), one L2 round for everything
//  - both batches' transcendentals + fixed-point candidates in the load
//    shadow; post-mask path is SEL + SEL + IADD -> REDUX.SUM
//  - integer REDUX at both reduction levels (sm_103a: int REDUX only)
//  - split named barrier with only 8 arrivals; warp 0 finishes alone

#define FPSCALE 65536.0f

__global__ void fused_segenc_loss_kernel(const float* __restrict__ preds,
                                         const int*   __restrict__ targets,
                                         float* __restrict__ out,
                                         int B, int C, int n_per_batch,
                                         float out_scale) {
    __shared__ int warp_sums[16];

    const int t      = threadIdx.x;
    const int w      = t >> 5;
    const int lane   = t & 31;
    const int nwarps = blockDim.x >> 5;
    const unsigned int full_mask = (1u << C) - 1u;
    const bool vec_ok = ((n_per_batch & 3) == 0);
    const int total4  = n_per_batch >> 2;

    int ai = 0;

    if (vec_ok && B <= 2 * nwarps) {
        // ======== fast path: up to 2 batches per warp, straight-line ======
        const int b0 = w;
        const int b1 = w + nwarps;
        const bool h0 = b0 < B;
        const bool h1 = b1 < B;
        const int limit = min(64, total4);
        const bool p0 = lane < limit;
        const bool p1 = lane + 32 < limit;

        // ---- issue all sample loads back-to-back (MLP 4)
        int4 v00 = make_int4(0,0,0,0), v01 = make_int4(0,0,0,0);
        int4 v10 = make_int4(0,0,0,0), v11 = make_int4(0,0,0,0);
        if (h0) {
            const int4* __restrict__ a0 =
                reinterpret_cast<const int4*>(targets) + (size_t)b0 * total4;
            if (p0) v00 = a0[lane];
            if (p1) v01 = a0[lane + 32];
        }
        if (h1) {
            const int4* __restrict__ a1 =
                reinterpret_cast<const int4*>(targets) + (size_t)b1 * total4;
            if (p0) v10 = a1[lane];
            if (p1) v11 = a1[lane + 32];
        }

        // ---- preds + transcendentals + fixed-point candidates (load shadow)
        float x0 = 0.0f, x1 = 0.0f;
        if (h0 && lane < C) x0 = __ldg(&preds[b0 * C + lane]);
        if (h1 && lane < C) x1 = __ldg(&preds[b1 * C + lane]);
        const float l0   = log1pf(expf(-fabsf(x0)));
        const float l1   = log1pf(expf(-fabsf(x1)));
        const int ip0 = __float2int_rn(-(fminf(x0, 0.0f) - l0) * FPSCALE);
        const int iq0 = __float2int_rn(-(fminf(-x0, 0.0f) - l0) * FPSCALE);
        const int ip1 = __float2int_rn(-(fminf(x1, 0.0f) - l1) * FPSCALE);
        const int iq1 = __float2int_rn(-(fminf(-x1, 0.0f) - l1) * FPSCALE);

        // ---- presence masks
        unsigned int m0 = 0u, m1 = 0u;
        if (p0) m0 |= (1u << (v00.x & 31)) | (1u << (v00.y & 31)) |
                      (1u << (v00.z & 31)) | (1u << (v00.w & 31));
        if (p1) m0 |= (1u << (v01.x & 31)) | (1u << (v01.y & 31)) |
                      (1u << (v01.z & 31)) | (1u << (v01.w & 31));
        if (p0) m1 |= (1u << (v10.x & 31)) | (1u << (v10.y & 31)) |
                      (1u << (v10.z & 31)) | (1u << (v10.w & 31));
        if (p1) m1 |= (1u << (v11.x & 31)) | (1u << (v11.y & 31)) |
                      (1u << (v11.z & 31)) | (1u << (v11.w & 31));
        unsigned int wm0 = __reduce_or_sync(0xffffffffu, m0);
        unsigned int wm1 = __reduce_or_sync(0xffffffffu, m1);

        // ---- rare fallback: scan own batch, warp-uniform early exit
        if (h0 && (wm0 & full_mask) != full_mask) {
            const int* __restrict__ tb = targets + (size_t)b0 * n_per_batch;
            for (int base = 0; base < n_per_batch; base += 4096) {
                const int end = min(base + 4096, n_per_batch);
                unsigned int mm = 0u;
                for (int i = base + lane; i < end; i += 32)
                    mm |= 1u << (tb[i] & 31);
                wm0 |= __reduce_or_sync(0xffffffffu, mm);
                if ((wm0 & full_mask) == full_mask) break;
            }
        }
        if (h1 && (wm1 & full_mask) != full_mask) {
            const int* __restrict__ tb = targets + (size_t)b1 * n_per_batch;
            for (int base = 0; base < n_per_batch; base += 4096) {
                const int end = min(base + 4096, n_per_batch);
                unsigned int mm = 0u;
                for (int i = base + lane; i < end; i += 32)
                    mm |= 1u << (tb[i] & 31);
                wm1 |= __reduce_or_sync(0xffffffffu, mm);
                if ((wm1 & full_mask) == full_mask) break;
            }
        }

        // ---- post-mask path: selects + add
        if (lane < C) {
            if (h0) ai  = ((wm0 >> lane) & 1u) ? ip0 : iq0;
            if (h1) ai += ((wm1 >> lane) & 1u) ? ip1 : iq1;
        }
    } else {
        // ======== generic path: scalar loop, any shape ========
        float acc = 0.0f;
        for (int bb = w; bb < B; bb += nwarps) {
            float x = 0.0f;
            if (lane < C) x = __ldg(&preds[bb * C + lane]);
            const float l   = log1pf(expf(-fabsf(x)));
            const float lsp = fminf(x, 0.0f) - l;
            const float lsn = fminf(-x, 0.0f) - l;

            unsigned int wm = 0u;
            const int* __restrict__ tb = targets + (size_t)bb * n_per_batch;
            for (int base = 0; base < n_per_batch; base += 4096) {
                const int end = min(base + 4096, n_per_batch);
                unsigned int mm = 0u;
                for (int i = base + lane; i < end; i += 32)
                    mm |= 1u << (tb[i] & 31);
                wm |= __reduce_or_sync(0xffffffffu, mm);
                if ((wm & full_mask) == full_mask) break;
            }
            if (lane < C) acc += -(((wm >> lane) & 1u) ? lsp : lsn);
        }
        ai = __float2int_rn(acc * FPSCALE);
    }

    // ---- warp sum: single REDUX.SUM, store partial
    const int wsum = __reduce_add_sync(0xffffffffu, ai);
    if (lane == 0) warp_sums[w] = wsum;

    // ---- split barrier: warps 1..7 arrive and retire; warp 0 syncs and
    //      reduces the 8 partials with one more REDUX.
    const unsigned int nthreads = blockDim.x;
    if (w != 0) {
        asm volatile("bar.arrive 1, %0;" :: "r"(nthreads) : "memory");
    } else {
        asm volatile("bar.sync 1, %0;" :: "r"(nthreads) : "memory");
        const int p = (lane < nwarps) ? warp_sums[lane] : 0;
        const int s = __reduce_add_sync(0xffffffffu, p);
        if (lane == 0) out[0] = (float)s * out_scale;
    }
}

extern "C" void kernel_launch(void* const* d_in, const int* in_sizes, int n_in,
                              void* d_out, int out_size) {
    const float* preds   = (const float*)d_in[0];
    const int*   targets = (const int*)d_in[1];

    const int C = 19;                       // NUM_CLASSES (fixed by problem)
    const int B = in_sizes[0] / C;          // 16
    const int n_per_batch = in_sizes[1] / B;
    const float out_scale = 1.0f / ((float)(B * C) * FPSCALE);

    fused_segenc_loss_kernel<<<1, 256>>>(preds, targets, (float*)d_out,
                                         B, C, n_per_batch, out_scale);
}